// round 4
// baseline (speedup 1.0000x reference)
#include <cuda_runtime.h>

// ---------------- problem constants ----------------
constexpr int Bsz = 4;
constexpr int Np  = 2304;   // H*W = 48*48
constexpr int Cc  = 2304;   // channels = embed
constexpr int Ee  = 2304;
constexpr int E2  = 4608;   // 2*E

// ---------------- scratch (device globals; allocation-free) ----------------
__device__ float g_y1p  [(size_t)Bsz*Cc*2500];        // relu(conv1), zero-padded 50x50
__device__ float g_w2t  [(size_t)9*Cc*Cc];            // conv2 weights re-laid [kk][o][c]
__device__ float g_down [(size_t)Bsz*Cc*Np];
__device__ float g_q    [(size_t)Bsz*Cc*Np];
__device__ float g_k2   [(size_t)Bsz*Cc*Np];
__device__ float g_v2   [(size_t)Bsz*Cc*Np];
__device__ float g_qk   [(size_t)Bsz*Cc*Np];          // qk -> softmax in place
__device__ float g_h1pre[(size_t)Bsz*Cc*Np];          // scatter(ao)+down
__device__ float g_h1   [(size_t)Bsz*Cc*Np];          // after LN1
__device__ float g_f1   [(size_t)Bsz*Cc*(size_t)E2];  // ffn hidden

// ---------------- conv1 (CIN=1) + ReLU, written into padded buffer ----------------
__global__ void conv1_pad_kernel(const float* __restrict__ x,
                                 const float* __restrict__ w1,
                                 const float* __restrict__ b1)
{
    int idx = blockIdx.x * blockDim.x + threadIdx.x;
    if (idx >= Bsz * Cc * 2500) return;
    int pp = idx % 2500;
    int bc = idx / 2500;
    int c  = bc % Cc;
    int b  = bc / Cc;
    int ph = pp / 50, pw = pp % 50;
    float v = 0.f;
    if (ph >= 1 && ph <= 48 && pw >= 1 && pw <= 48) {
        int h = ph - 1, w = pw - 1;
        const float* xb = x + (size_t)b * 2304;
        const float* wc = w1 + (size_t)c * 9;
        float s = b1[c];
        #pragma unroll
        for (int kh = 0; kh < 3; kh++) {
            int hy = h + kh - 1;
            if (hy < 0 || hy >= 48) continue;
            #pragma unroll
            for (int kw = 0; kw < 3; kw++) {
                int wx = w + kw - 1;
                if (wx < 0 || wx >= 48) continue;
                s += wc[kh*3+kw] * xb[hy*48 + wx];
            }
        }
        v = fmaxf(s, 0.f);
    }
    g_y1p[idx] = v;
}

// ---------------- conv2 weight re-layout: w2[o][c][kk] -> w2t[kk][o][c] ----------------
__global__ void w2t_kernel(const float* __restrict__ w2)
{
    __shared__ float sm[2304];
    int base = blockIdx.x * 256;        // (o*Cc+c) row block
    int t = threadIdx.x;
    for (int i = t; i < 2304; i += 256)
        sm[i] = w2[(size_t)base * 9 + i];
    __syncthreads();
    size_t r = (size_t)base + t;
    #pragma unroll
    for (int kk = 0; kk < 9; kk++)
        g_w2t[(size_t)kk * Cc * Cc + r] = sm[t * 9 + kk];
}

// ---------------- conv2 implicit GEMM (+identity, +relu) -> down ----------------
__global__ __launch_bounds__(256) void conv2_kernel(
    const float* __restrict__ x,
    const float* __restrict__ c2b,
    const float* __restrict__ idw,
    const float* __restrict__ idb)
{
    int b = blockIdx.z;
    int row0 = blockIdx.y * 128, col0 = blockIdx.x * 128;
    int tid = threadIdx.x;
    int tx = tid & 15, ty = tid >> 4;
    __shared__ float As[8][128];
    __shared__ float Bs[8][128];
    float acc[8][8] = {};
    const float* Ypb = g_y1p + (size_t)b * Cc * 2500;

    int arow = tid >> 1, akc = (tid & 1) * 4;
    int bk   = tid >> 5, bcol = (tid & 31) * 4;
    int p0c  = col0 + bcol;
    int ph = p0c / 48, pw = p0c - ph * 48;

    #pragma unroll 1
    for (int kk = 0; kk < 9; kk++) {
        int kh = kk / 3, kw = kk - kh * 3;
        const float* Ak = g_w2t + (size_t)kk * Cc * Cc;
        int off0 = (ph + kh) * 50 + pw + kw;
        #pragma unroll 1
        for (int c0 = 0; c0 < Cc; c0 += 8) {
            float4 av = *(const float4*)(Ak + (size_t)(row0 + arow) * Cc + c0 + akc);
            As[akc+0][arow] = av.x; As[akc+1][arow] = av.y;
            As[akc+2][arow] = av.z; As[akc+3][arow] = av.w;
            const float* bp = Ypb + (size_t)(c0 + bk) * 2500 + off0;
            Bs[bk][bcol+0] = bp[0]; Bs[bk][bcol+1] = bp[1];
            Bs[bk][bcol+2] = bp[2]; Bs[bk][bcol+3] = bp[3];
            __syncthreads();
            #pragma unroll
            for (int k = 0; k < 8; k++) {
                float ar[8], br[8];
                *(float4*)&ar[0] = *(const float4*)&As[k][ty*8];
                *(float4*)&ar[4] = *(const float4*)&As[k][ty*8+4];
                *(float4*)&br[0] = *(const float4*)&Bs[k][tx*8];
                *(float4*)&br[4] = *(const float4*)&Bs[k][tx*8+4];
                #pragma unroll
                for (int i = 0; i < 8; i++)
                    #pragma unroll
                    for (int j = 0; j < 8; j++)
                        acc[i][j] = fmaf(ar[i], br[j], acc[i][j]);
            }
            __syncthreads();
        }
    }

    const float* xb = x + (size_t)b * 2304;
    #pragma unroll
    for (int i = 0; i < 8; i++) {
        int o = row0 + ty*8 + i;
        float cb = c2b[o], iw_ = idw[o], ib = idb[o];
        float* dst = g_down + ((size_t)b * Cc + o) * Np;
        #pragma unroll
        for (int j = 0; j < 8; j++) {
            int p = col0 + tx*8 + j;
            float v = acc[i][j] + cb + iw_ * xb[p] + ib;
            dst[p] = fmaxf(v, 0.f);
        }
    }
}

// ---------------- generic 128x128x8 SGEMM with epilogue variants ----------------
// EPI 0: +p0[row]                          (q/k/v bias)
// EPI 1: relu(+p0[col])                    (ffn1)
// EPI 2: +p0[col] + p1[row*ldc+col]        (ffn2 + residual)
// EPI 3: *1/48 + relpos bias               (qk)
// EPI 4: scatter (permute view) + p0[g*N+n] residual (attn@v)
template<int TB, int EPI>
__global__ __launch_bounds__(256) void gemm128(
    const float* __restrict__ Ag, const float* __restrict__ Bg, float* __restrict__ Cg,
    int K, int lda, int ldb, int ldc,
    size_t sA, size_t sB, size_t sC,
    const float* __restrict__ p0, const float* __restrict__ p1)
{
    int b = blockIdx.z;
    const float* A  = Ag + (size_t)b * sA;
    const float* Bm = Bg + (size_t)b * sB;
    float* Cp = Cg + (size_t)b * sC;
    int row0 = blockIdx.y * 128, col0 = blockIdx.x * 128;
    int tid = threadIdx.x;
    int tx = tid & 15, ty = tid >> 4;
    __shared__ float As[8][128];
    __shared__ float Bs[8][128];
    float acc[8][8] = {};
    int arow = tid >> 1, akc = (tid & 1) * 4;
    int bkr  = tid >> 5, bcol = (tid & 31) * 4;

    #pragma unroll 1
    for (int k0 = 0; k0 < K; k0 += 8) {
        float4 av = *(const float4*)(A + (size_t)(row0 + arow) * lda + k0 + akc);
        As[akc+0][arow] = av.x; As[akc+1][arow] = av.y;
        As[akc+2][arow] = av.z; As[akc+3][arow] = av.w;
        if (TB == 0) {
            float4 bv = *(const float4*)(Bm + (size_t)(k0 + bkr) * ldb + col0 + bcol);
            *(float4*)&Bs[bkr][bcol] = bv;
        } else {
            float4 bv = *(const float4*)(Bm + (size_t)(col0 + arow) * ldb + k0 + akc);
            Bs[akc+0][arow] = bv.x; Bs[akc+1][arow] = bv.y;
            Bs[akc+2][arow] = bv.z; Bs[akc+3][arow] = bv.w;
        }
        __syncthreads();
        #pragma unroll
        for (int k = 0; k < 8; k++) {
            float ar[8], br[8];
            *(float4*)&ar[0] = *(const float4*)&As[k][ty*8];
            *(float4*)&ar[4] = *(const float4*)&As[k][ty*8+4];
            *(float4*)&br[0] = *(const float4*)&Bs[k][tx*8];
            *(float4*)&br[4] = *(const float4*)&Bs[k][tx*8+4];
            #pragma unroll
            for (int i = 0; i < 8; i++)
                #pragma unroll
                for (int j = 0; j < 8; j++)
                    acc[i][j] = fmaf(ar[i], br[j], acc[i][j]);
        }
        __syncthreads();
    }

    #pragma unroll
    for (int i = 0; i < 8; i++) {
        int m = row0 + ty*8 + i;
        #pragma unroll
        for (int j = 0; j < 8; j++) {
            int n = col0 + tx*8 + j;
            float v = acc[i][j];
            if (EPI == 0) {
                Cp[(size_t)m * ldc + n] = v + p0[m];
            } else if (EPI == 1) {
                Cp[(size_t)m * ldc + n] = fmaxf(v + p0[n], 0.f);
            } else if (EPI == 2) {
                Cp[(size_t)m * ldc + n] = v + p0[n] + p1[(size_t)m * ldc + n];
            } else if (EPI == 3) {
                v *= 0.0208333333333333f;           // 1/sqrt(2304)
                int ih = m / 48, iw = m - ih * 48;
                int jh = n / 48, jw = n - jh * 48;
                int ridx = (ih - jh + 47) * 95 + (iw - jw + 47);
                Cp[(size_t)m * ldc + n] = v + p0[ridx * 4 + b];
            } else { // EPI 4: permute(1,0,2).view scatter + down residual
                int g = (m / 576) * Cc + (m - (m / 576) * 576) * 4 + b;
                size_t o = (size_t)g * Np + n;
                Cp[o] = v + p0[o];
            }
        }
    }
}

// ---------------- softmax over last dim (2304), in place on g_qk ----------------
__global__ void softmax_kernel()
{
    size_t row = blockIdx.x;
    float* p = g_qk + row * Np;
    int t = threadIdx.x;
    float v[9];
    float mx = -1e30f;
    #pragma unroll
    for (int i = 0; i < 9; i++) { v[i] = p[t + i*256]; mx = fmaxf(mx, v[i]); }
    __shared__ float red[256];
    red[t] = mx; __syncthreads();
    for (int s = 128; s > 0; s >>= 1) {
        if (t < s) red[t] = fmaxf(red[t], red[t+s]);
        __syncthreads();
    }
    mx = red[0]; __syncthreads();
    float sum = 0.f;
    #pragma unroll
    for (int i = 0; i < 9; i++) { v[i] = __expf(v[i] - mx); sum += v[i]; }
    red[t] = sum; __syncthreads();
    for (int s = 128; s > 0; s >>= 1) {
        if (t < s) red[t] += red[t+s];
        __syncthreads();
    }
    float inv = 1.0f / red[0];
    #pragma unroll
    for (int i = 0; i < 9; i++) p[t + i*256] = v[i] * inv;
}

// ---------------- LayerNorm over rows of 2304 ----------------
__global__ void ln_kernel(const float* __restrict__ in, float* __restrict__ out,
                          const float* __restrict__ gam, const float* __restrict__ bet)
{
    size_t row = blockIdx.x;
    const float* p = in + row * Ee;
    float* q = out + row * Ee;
    int t = threadIdx.x;
    float v[9];
    float s = 0.f;
    #pragma unroll
    for (int i = 0; i < 9; i++) { v[i] = p[t + i*256]; s += v[i]; }
    __shared__ float red[256];
    red[t] = s; __syncthreads();
    for (int st = 128; st > 0; st >>= 1) {
        if (t < st) red[t] += red[t+st];
        __syncthreads();
    }
    float mu = red[0] * (1.f / 2304.f); __syncthreads();
    float s2 = 0.f;
    #pragma unroll
    for (int i = 0; i < 9; i++) { float d = v[i] - mu; s2 += d * d; }
    red[t] = s2; __syncthreads();
    for (int st = 128; st > 0; st >>= 1) {
        if (t < st) red[t] += red[t+st];
        __syncthreads();
    }
    float rs = rsqrtf(red[0] * (1.f / 2304.f) + 1e-5f);
    #pragma unroll
    for (int i = 0; i < 9; i++) {
        int n = t + i*256;
        q[n] = (v[i] - mu) * rs * gam[n] + bet[n];
    }
}

// ---------------- maxpool 2x2 ----------------
__global__ void maxpool_kernel(const float* __restrict__ in, float* __restrict__ out)
{
    int idx = blockIdx.x * blockDim.x + threadIdx.x;
    if (idx >= Bsz * Cc * 576) return;
    int r  = idx % 576;
    int bc = idx / 576;
    int i = r / 24, j = r % 24;
    const float* pp = in + (size_t)bc * 2304 + (2*i) * 48 + 2*j;
    out[idx] = fmaxf(fmaxf(pp[0], pp[1]), fmaxf(pp[48], pp[49]));
}

// ---------------- launch ----------------
extern "C" void kernel_launch(void* const* d_in, const int* in_sizes, int n_in,
                              void* d_out, int out_size)
{
    (void)in_sizes; (void)n_in; (void)out_size;
    const float* x       = (const float*)d_in[0];
    const float* conv1_w = (const float*)d_in[1];
    const float* conv1_b = (const float*)d_in[2];
    const float* conv2_w = (const float*)d_in[3];
    const float* conv2_b = (const float*)d_in[4];
    const float* id_w    = (const float*)d_in[5];
    const float* id_b    = (const float*)d_in[6];
    const float* q_w     = (const float*)d_in[7];
    const float* q_b     = (const float*)d_in[8];
    const float* k_w     = (const float*)d_in[9];
    const float* k_b     = (const float*)d_in[10];
    const float* v_w     = (const float*)d_in[11];
    const float* v_b     = (const float*)d_in[12];
    const float* rel_tab = (const float*)d_in[13];
    const float* ln1_g   = (const float*)d_in[14];
    const float* ln1_b   = (const float*)d_in[15];
    const float* ln2_g   = (const float*)d_in[16];
    const float* ln2_b   = (const float*)d_in[17];
    const float* ffn_w1  = (const float*)d_in[18];
    const float* ffn_b1  = (const float*)d_in[19];
    const float* ffn_w2  = (const float*)d_in[20];
    const float* ffn_b2  = (const float*)d_in[21];

    float* out  = (float*)d_out;
    float* pout = out + (size_t)Bsz * Cc * Np;

    float *pdown, *pq, *pk, *pv, *pqk, *ph1pre, *ph1, *pf1;
    cudaGetSymbolAddress((void**)&pdown,  g_down);
    cudaGetSymbolAddress((void**)&pq,     g_q);
    cudaGetSymbolAddress((void**)&pk,     g_k2);
    cudaGetSymbolAddress((void**)&pv,     g_v2);
    cudaGetSymbolAddress((void**)&pqk,    g_qk);
    cudaGetSymbolAddress((void**)&ph1pre, g_h1pre);
    cudaGetSymbolAddress((void**)&ph1,    g_h1);
    cudaGetSymbolAddress((void**)&pf1,    g_f1);

    const size_t sm = (size_t)Cc * Np;   // per-batch plane stride

    conv1_pad_kernel<<<(Bsz*Cc*2500 + 255)/256, 256>>>(x, conv1_w, conv1_b);
    w2t_kernel<<<Cc*Cc/256, 256>>>(conv2_w);
    conv2_kernel<<<dim3(18,18,Bsz), 256>>>(x, conv2_b, id_w, id_b);

    // q,k,v = W @ down + bias     (M=E, K=C, N=Np, batched over B)
    gemm128<0,0><<<dim3(18,18,Bsz), 256>>>(q_w, pdown, pq, Cc, Cc, Np, Np, 0, sm, sm, q_b, nullptr);
    gemm128<0,0><<<dim3(18,18,Bsz), 256>>>(k_w, pdown, pk, Cc, Cc, Np, Np, 0, sm, sm, k_b, nullptr);
    gemm128<0,0><<<dim3(18,18,Bsz), 256>>>(v_w, pdown, pv, Cc, Cc, Np, Np, 0, sm, sm, v_b, nullptr);

    // qk = (q @ k^T)/48 + relpos bias
    gemm128<1,3><<<dim3(18,18,Bsz), 256>>>(pq, pk, pqk, Np, Np, Np, Ee, sm, sm, sm, rel_tab, nullptr);

    softmax_kernel<<<Bsz*Ee, 256>>>();

    // h1pre = scatter(attn @ v) + down
    gemm128<0,4><<<dim3(18,18,Bsz), 256>>>(pqk, pv, ph1pre, Ee, Ee, Np, Np, sm, sm, 0, pdown, nullptr);

    ln_kernel<<<Bsz*Cc, 256>>>(ph1pre, ph1, ln1_g, ln1_b);

    // ffn1: (9216 x 2304) @ (2304 x 4608), relu + bias
    gemm128<0,1><<<dim3(36,72,1), 256>>>(ph1, ffn_w1, pf1, Ee, Ee, E2, E2, 0, 0, 0, ffn_b1, nullptr);
    // ffn2: (9216 x 4608) @ (4608 x 2304) + bias + h1 residual -> d_out (pre-LN2)
    gemm128<0,2><<<dim3(18,72,1), 256>>>(pf1, ffn_w2, out, E2, E2, Np, Np, 0, 0, 0, ffn_b2, ph1);

    ln_kernel<<<Bsz*Cc, 256>>>(out, out, ln2_g, ln2_b);
    maxpool_kernel<<<(Bsz*Cc*576 + 255)/256, 256>>>(out, pout);
}

// round 5
// speedup vs baseline: 1.0521x; 1.0521x over previous
#include <cuda_runtime.h>

// ---------------- problem constants ----------------
constexpr int Bsz = 4;
constexpr int Np  = 2304;   // H*W = 48*48
constexpr int Cc  = 2304;   // channels = embed
constexpr int Ee  = 2304;
constexpr int E2  = 4608;   // 2*E

// ---------------- scratch (device globals; allocation-free) ----------------
__device__ float g_y1p  [(size_t)Bsz*Cc*2500];        // relu(conv1), zero-padded 50x50
__device__ float g_w2t  [(size_t)9*Cc*Cc];            // conv2 weights re-laid [kk][o][c]
__device__ float g_down [(size_t)Bsz*Cc*Np];
__device__ float g_q    [(size_t)Bsz*Cc*Np];
__device__ float g_k2   [(size_t)Bsz*Cc*Np];
__device__ float g_v2   [(size_t)Bsz*Cc*Np];
__device__ float g_qk   [(size_t)Bsz*Cc*Np];          // qk -> softmax in place
__device__ float g_h1pre[(size_t)Bsz*Cc*Np];          // scatter(ao)+down
__device__ float g_h1   [(size_t)Bsz*Cc*Np];          // after LN1
__device__ float g_f1   [(size_t)Bsz*Cc*(size_t)E2];  // ffn hidden

// ---------------- conv1 (CIN=1) + ReLU, written into padded buffer ----------------
__global__ void conv1_pad_kernel(const float* __restrict__ x,
                                 const float* __restrict__ w1,
                                 const float* __restrict__ b1)
{
    int idx = blockIdx.x * blockDim.x + threadIdx.x;
    if (idx >= Bsz * Cc * 2500) return;
    int pp = idx % 2500;
    int bc = idx / 2500;
    int c  = bc % Cc;
    int b  = bc / Cc;
    int ph = pp / 50, pw = pp % 50;
    float v = 0.f;
    if (ph >= 1 && ph <= 48 && pw >= 1 && pw <= 48) {
        int h = ph - 1, w = pw - 1;
        const float* xb = x + (size_t)b * 2304;
        const float* wc = w1 + (size_t)c * 9;
        float s = b1[c];
        #pragma unroll
        for (int kh = 0; kh < 3; kh++) {
            int hy = h + kh - 1;
            if (hy < 0 || hy >= 48) continue;
            #pragma unroll
            for (int kw = 0; kw < 3; kw++) {
                int wx = w + kw - 1;
                if (wx < 0 || wx >= 48) continue;
                s += wc[kh*3+kw] * xb[hy*48 + wx];
            }
        }
        v = fmaxf(s, 0.f);
    }
    g_y1p[idx] = v;
}

// ---------------- conv2 weight re-layout: w2[o][c][kk] -> w2t[kk][o][c] ----------------
__global__ void w2t_kernel(const float* __restrict__ w2)
{
    __shared__ float sm[2304];
    int base = blockIdx.x * 256;        // (o*Cc+c) row block
    int t = threadIdx.x;
    for (int i = t; i < 2304; i += 256)
        sm[i] = w2[(size_t)base * 9 + i];
    __syncthreads();
    size_t r = (size_t)base + t;
    #pragma unroll
    for (int kk = 0; kk < 9; kk++)
        g_w2t[(size_t)kk * Cc * Cc + r] = sm[t * 9 + kk];
}

// ---------------- conv2 implicit GEMM (+identity, +relu) -> down ----------------
__global__ __launch_bounds__(256) void conv2_kernel(
    const float* __restrict__ x,
    const float* __restrict__ c2b,
    const float* __restrict__ idw,
    const float* __restrict__ idb)
{
    int b = blockIdx.z;
    int row0 = blockIdx.y * 128, col0 = blockIdx.x * 128;
    int tid = threadIdx.x;
    int tx = tid & 15, ty = tid >> 4;
    __shared__ float As[8][128];
    __shared__ float Bs[8][128];
    float acc[8][8] = {};
    const float* Ypb = g_y1p + (size_t)b * Cc * 2500;

    int arow = tid >> 1, akc = (tid & 1) * 4;
    int bk   = tid >> 5, bcol = (tid & 31) * 4;
    int p0c  = col0 + bcol;
    int ph = p0c / 48, pw = p0c - ph * 48;

    #pragma unroll 1
    for (int kk = 0; kk < 9; kk++) {
        int kh = kk / 3, kw = kk - kh * 3;
        const float* Ak = g_w2t + (size_t)kk * Cc * Cc;
        int off0 = (ph + kh) * 50 + pw + kw;
        #pragma unroll 1
        for (int c0 = 0; c0 < Cc; c0 += 8) {
            float4 av = *(const float4*)(Ak + (size_t)(row0 + arow) * Cc + c0 + akc);
            As[akc+0][arow] = av.x; As[akc+1][arow] = av.y;
            As[akc+2][arow] = av.z; As[akc+3][arow] = av.w;
            const float* bp = Ypb + (size_t)(c0 + bk) * 2500 + off0;
            Bs[bk][bcol+0] = bp[0]; Bs[bk][bcol+1] = bp[1];
            Bs[bk][bcol+2] = bp[2]; Bs[bk][bcol+3] = bp[3];
            __syncthreads();
            #pragma unroll
            for (int k = 0; k < 8; k++) {
                float ar[8], br[8];
                *(float4*)&ar[0] = *(const float4*)&As[k][ty*8];
                *(float4*)&ar[4] = *(const float4*)&As[k][ty*8+4];
                *(float4*)&br[0] = *(const float4*)&Bs[k][tx*8];
                *(float4*)&br[4] = *(const float4*)&Bs[k][tx*8+4];
                #pragma unroll
                for (int i = 0; i < 8; i++)
                    #pragma unroll
                    for (int j = 0; j < 8; j++)
                        acc[i][j] = fmaf(ar[i], br[j], acc[i][j]);
            }
            __syncthreads();
        }
    }

    const float* xb = x + (size_t)b * 2304;
    #pragma unroll
    for (int i = 0; i < 8; i++) {
        int o = row0 + ty*8 + i;
        float cb = c2b[o], iw_ = idw[o], ib = idb[o];
        float* dst = g_down + ((size_t)b * Cc + o) * Np;
        #pragma unroll
        for (int j = 0; j < 8; j++) {
            int p = col0 + tx*8 + j;
            float v = acc[i][j] + cb + iw_ * xb[p] + ib;
            dst[p] = fmaxf(v, 0.f);
        }
    }
}

// ---------------- generic 128x128x8 SGEMM with epilogue variants ----------------
// EPI 0: +p0[row]                          (q/k/v bias)
// EPI 1: relu(+p0[col])                    (ffn1)
// EPI 2: +p0[col] + p1[row*ldc+col]        (ffn2 + residual)
// EPI 3: *1/48 + relpos bias               (qk)
// EPI 4: scatter (permute view) + p0[g*N+n] residual (attn@v)
template<int TB, int EPI>
__global__ __launch_bounds__(256) void gemm128(
    const float* __restrict__ Ag, const float* __restrict__ Bg, float* __restrict__ Cg,
    int K, int lda, int ldb, int ldc,
    size_t sA, size_t sB, size_t sC,
    const float* __restrict__ p0, const float* __restrict__ p1)
{
    int b = blockIdx.z;
    const float* A  = Ag + (size_t)b * sA;
    const float* Bm = Bg + (size_t)b * sB;
    float* Cp = Cg + (size_t)b * sC;
    int row0 = blockIdx.y * 128, col0 = blockIdx.x * 128;
    int tid = threadIdx.x;
    int tx = tid & 15, ty = tid >> 4;
    __shared__ float As[8][128];
    __shared__ float Bs[8][128];
    float acc[8][8] = {};
    int arow = tid >> 1, akc = (tid & 1) * 4;
    int bkr  = tid >> 5, bcol = (tid & 31) * 4;

    #pragma unroll 1
    for (int k0 = 0; k0 < K; k0 += 8) {
        float4 av = *(const float4*)(A + (size_t)(row0 + arow) * lda + k0 + akc);
        As[akc+0][arow] = av.x; As[akc+1][arow] = av.y;
        As[akc+2][arow] = av.z; As[akc+3][arow] = av.w;
        if (TB == 0) {
            float4 bv = *(const float4*)(Bm + (size_t)(k0 + bkr) * ldb + col0 + bcol);
            *(float4*)&Bs[bkr][bcol] = bv;
        } else {
            float4 bv = *(const float4*)(Bm + (size_t)(col0 + arow) * ldb + k0 + akc);
            Bs[akc+0][arow] = bv.x; Bs[akc+1][arow] = bv.y;
            Bs[akc+2][arow] = bv.z; Bs[akc+3][arow] = bv.w;
        }
        __syncthreads();
        #pragma unroll
        for (int k = 0; k < 8; k++) {
            float ar[8], br[8];
            *(float4*)&ar[0] = *(const float4*)&As[k][ty*8];
            *(float4*)&ar[4] = *(const float4*)&As[k][ty*8+4];
            *(float4*)&br[0] = *(const float4*)&Bs[k][tx*8];
            *(float4*)&br[4] = *(const float4*)&Bs[k][tx*8+4];
            #pragma unroll
            for (int i = 0; i < 8; i++)
                #pragma unroll
                for (int j = 0; j < 8; j++)
                    acc[i][j] = fmaf(ar[i], br[j], acc[i][j]);
        }
        __syncthreads();
    }

    #pragma unroll
    for (int i = 0; i < 8; i++) {
        int m = row0 + ty*8 + i;
        #pragma unroll
        for (int j = 0; j < 8; j++) {
            int n = col0 + tx*8 + j;
            float v = acc[i][j];
            if (EPI == 0) {
                Cp[(size_t)m * ldc + n] = v + p0[m];
            } else if (EPI == 1) {
                Cp[(size_t)m * ldc + n] = fmaxf(v + p0[n], 0.f);
            } else if (EPI == 2) {
                Cp[(size_t)m * ldc + n] = v + p0[n] + p1[(size_t)m * ldc + n];
            } else if (EPI == 3) {
                v *= 0.0208333333333333f;           // 1/sqrt(2304)
                int ih = m / 48, iw = m - ih * 48;
                int jh = n / 48, jw = n - jh * 48;
                int ridx = (ih - jh + 47) * 95 + (iw - jw + 47);
                Cp[(size_t)m * ldc + n] = v + p0[ridx * 4 + b];
            } else { // EPI 4: permute(1,0,2).view scatter + down residual
                int g = (m / 576) * Cc + (m - (m / 576) * 576) * 4 + b;
                size_t o = (size_t)g * Np + n;
                Cp[o] = v + p0[o];
            }
        }
    }
}

// ---------------- softmax over last dim (2304), in place on g_qk ----------------
__global__ void softmax_kernel()
{
    size_t row = blockIdx.x;
    float* p = g_qk + row * Np;
    int t = threadIdx.x;
    float v[9];
    float mx = -1e30f;
    #pragma unroll
    for (int i = 0; i < 9; i++) { v[i] = p[t + i*256]; mx = fmaxf(mx, v[i]); }
    __shared__ float red[256];
    red[t] = mx; __syncthreads();
    for (int s = 128; s > 0; s >>= 1) {
        if (t < s) red[t] = fmaxf(red[t], red[t+s]);
        __syncthreads();
    }
    mx = red[0]; __syncthreads();
    float sum = 0.f;
    #pragma unroll
    for (int i = 0; i < 9; i++) { v[i] = __expf(v[i] - mx); sum += v[i]; }
    red[t] = sum; __syncthreads();
    for (int s = 128; s > 0; s >>= 1) {
        if (t < s) red[t] += red[t+s];
        __syncthreads();
    }
    float inv = 1.0f / red[0];
    #pragma unroll
    for (int i = 0; i < 9; i++) p[t + i*256] = v[i] * inv;
}

// ---------------- LayerNorm over rows of 2304 ----------------
__global__ void ln_kernel(const float* __restrict__ in, float* __restrict__ out,
                          const float* __restrict__ gam, const float* __restrict__ bet)
{
    size_t row = blockIdx.x;
    const float* p = in + row * Ee;
    float* q = out + row * Ee;
    int t = threadIdx.x;
    float v[9];
    float s = 0.f;
    #pragma unroll
    for (int i = 0; i < 9; i++) { v[i] = p[t + i*256]; s += v[i]; }
    __shared__ float red[256];
    red[t] = s; __syncthreads();
    for (int st = 128; st > 0; st >>= 1) {
        if (t < st) red[t] += red[t+st];
        __syncthreads();
    }
    float mu = red[0] * (1.f / 2304.f); __syncthreads();
    float s2 = 0.f;
    #pragma unroll
    for (int i = 0; i < 9; i++) { float d = v[i] - mu; s2 += d * d; }
    red[t] = s2; __syncthreads();
    for (int st = 128; st > 0; st >>= 1) {
        if (t < st) red[t] += red[t+st];
        __syncthreads();
    }
    float rs = rsqrtf(red[0] * (1.f / 2304.f) + 1e-5f);
    #pragma unroll
    for (int i = 0; i < 9; i++) {
        int n = t + i*256;
        q[n] = (v[i] - mu) * rs * gam[n] + bet[n];
    }
}

// ---------------- maxpool 2x2 ----------------
__global__ void maxpool_kernel(const float* __restrict__ in, float* __restrict__ out)
{
    int idx = blockIdx.x * blockDim.x + threadIdx.x;
    if (idx >= Bsz * Cc * 576) return;
    int r  = idx % 576;
    int bc = idx / 576;
    int i = r / 24, j = r % 24;
    const float* pp = in + (size_t)bc * 2304 + (2*i) * 48 + 2*j;
    out[idx] = fmaxf(fmaxf(pp[0], pp[1]), fmaxf(pp[48], pp[49]));
}

// ---------------- launch ----------------
extern "C" void kernel_launch(void* const* d_in, const int* in_sizes, int n_in,
                              void* d_out, int out_size)
{
    (void)in_sizes; (void)n_in; (void)out_size;
    const float* x       = (const float*)d_in[0];
    const float* conv1_w = (const float*)d_in[1];
    const float* conv1_b = (const float*)d_in[2];
    const float* conv2_w = (const float*)d_in[3];
    const float* conv2_b = (const float*)d_in[4];
    const float* id_w    = (const float*)d_in[5];
    const float* id_b    = (const float*)d_in[6];
    const float* q_w     = (const float*)d_in[7];
    const float* q_b     = (const float*)d_in[8];
    const float* k_w     = (const float*)d_in[9];
    const float* k_b     = (const float*)d_in[10];
    const float* v_w     = (const float*)d_in[11];
    const float* v_b     = (const float*)d_in[12];
    const float* rel_tab = (const float*)d_in[13];
    const float* ln1_g   = (const float*)d_in[14];
    const float* ln1_b   = (const float*)d_in[15];
    const float* ln2_g   = (const float*)d_in[16];
    const float* ln2_b   = (const float*)d_in[17];
    const float* ffn_w1  = (const float*)d_in[18];
    const float* ffn_b1  = (const float*)d_in[19];
    const float* ffn_w2  = (const float*)d_in[20];
    const float* ffn_b2  = (const float*)d_in[21];

    float* out  = (float*)d_out;
    float* pout = out + (size_t)Bsz * Cc * Np;

    float *pdown, *pq, *pk, *pv, *pqk, *ph1pre, *ph1, *pf1;
    cudaGetSymbolAddress((void**)&pdown,  g_down);
    cudaGetSymbolAddress((void**)&pq,     g_q);
    cudaGetSymbolAddress((void**)&pk,     g_k2);
    cudaGetSymbolAddress((void**)&pv,     g_v2);
    cudaGetSymbolAddress((void**)&pqk,    g_qk);
    cudaGetSymbolAddress((void**)&ph1pre, g_h1pre);
    cudaGetSymbolAddress((void**)&ph1,    g_h1);
    cudaGetSymbolAddress((void**)&pf1,    g_f1);

    const size_t sm = (size_t)Cc * Np;   // per-batch plane stride

    conv1_pad_kernel<<<(Bsz*Cc*2500 + 255)/256, 256>>>(x, conv1_w, conv1_b);
    w2t_kernel<<<Cc*Cc/256, 256>>>(conv2_w);
    conv2_kernel<<<dim3(18,18,Bsz), 256>>>(x, conv2_b, id_w, id_b);

    // q,k,v = W @ down + bias     (M=E, K=C, N=Np, batched over B)
    gemm128<0,0><<<dim3(18,18,Bsz), 256>>>(q_w, pdown, pq, Cc, Cc, Np, Np, 0, sm, sm, q_b, nullptr);
    gemm128<0,0><<<dim3(18,18,Bsz), 256>>>(k_w, pdown, pk, Cc, Cc, Np, Np, 0, sm, sm, k_b, nullptr);
    gemm128<0,0><<<dim3(18,18,Bsz), 256>>>(v_w, pdown, pv, Cc, Cc, Np, Np, 0, sm, sm, v_b, nullptr);

    // qk = (q @ k^T)/48 + relpos bias
    gemm128<1,3><<<dim3(18,18,Bsz), 256>>>(pq, pk, pqk, Np, Np, Np, Ee, sm, sm, sm, rel_tab, nullptr);

    softmax_kernel<<<Bsz*Ee, 256>>>();

    // h1pre = scatter(attn @ v) + down
    gemm128<0,4><<<dim3(18,18,Bsz), 256>>>(pqk, pv, ph1pre, Ee, Ee, Np, Np, sm, sm, 0, pdown, nullptr);

    ln_kernel<<<Bsz*Cc, 256>>>(ph1pre, ph1, ln1_g, ln1_b);

    // ffn1: (9216 x 2304) @ (2304 x 4608), relu + bias
    gemm128<0,1><<<dim3(36,72,1), 256>>>(ph1, ffn_w1, pf1, Ee, Ee, E2, E2, 0, 0, 0, ffn_b1, nullptr);
    // ffn2: (9216 x 4608) @ (4608 x 2304) + bias + h1 residual -> d_out (pre-LN2)
    gemm128<0,2><<<dim3(18,72,1), 256>>>(pf1, ffn_w2, out, E2, E2, Np, Np, 0, 0, 0, ffn_b2, ph1);

    ln_kernel<<<Bsz*Cc, 256>>>(out, out, ln2_g, ln2_b);
    maxpool_kernel<<<(Bsz*Cc*576 + 255)/256, 256>>>(out, pout);
}

// round 7
// speedup vs baseline: 3.5679x; 3.3911x over previous
#include <cuda_runtime.h>
#include <cuda_bf16.h>
#include <cstdint>

constexpr int Bsz = 4, Np = 2304, Cc = 2304, Ee = 2304, E2 = 4608, KW2 = 20736;
constexpr size_t PLANE = (size_t)Np * Cc;

// ---------------- scratch ----------------
__device__ __nv_bfloat16 gy_h[(size_t)Bsz*2500*2304], gy_l[(size_t)Bsz*2500*2304];
__device__ __nv_bfloat16 gw2_h[(size_t)2304*KW2],     gw2_l[(size_t)2304*KW2];
__device__ __nv_bfloat16 gqw_h[(size_t)2304*2304],    gqw_l[(size_t)2304*2304];
__device__ __nv_bfloat16 gkw_h[(size_t)2304*2304],    gkw_l[(size_t)2304*2304];
__device__ __nv_bfloat16 gvw_h[(size_t)2304*2304],    gvw_l[(size_t)2304*2304];
__device__ __nv_bfloat16 gw1t_h[(size_t)E2*Ee],       gw1t_l[(size_t)E2*Ee];
__device__ __nv_bfloat16 gw2f_h[(size_t)Ee*E2],       gw2f_l[(size_t)Ee*E2];
__device__ float         gdown[(size_t)Bsz*PLANE];                 // down^T fp32 [b][p][o]
__device__ __nv_bfloat16 gdt_h[(size_t)Bsz*PLANE],  gdt_l[(size_t)Bsz*PLANE];
__device__ __nv_bfloat16 gq_h[(size_t)Bsz*PLANE],   gq_l[(size_t)Bsz*PLANE];
__device__ __nv_bfloat16 gk_h[(size_t)Bsz*PLANE],   gk_l[(size_t)Bsz*PLANE];
__device__ __nv_bfloat16 gv_h[(size_t)Bsz*PLANE],   gv_l[(size_t)Bsz*PLANE];  // v^T [b][p][e]
__device__ float         gqk[(size_t)Bsz*PLANE];
__device__ __nv_bfloat16 gat_h[(size_t)Bsz*PLANE],  gat_l[(size_t)Bsz*PLANE];
__device__ float         gh1p[(size_t)Bsz*PLANE],   gh1[(size_t)Bsz*PLANE];
__device__ __nv_bfloat16 gh1_h[(size_t)Bsz*PLANE],  gh1_l[(size_t)Bsz*PLANE];
__device__ __nv_bfloat16 gf_h[(size_t)9216*E2],     gf_l[(size_t)9216*E2];

// ---------------- PTX helpers (all plain-sm_103-legal: cp.async / ldmatrix / mma.sync) ----------------
__device__ __forceinline__ uint32_t smem_u32(const void* p) {
    uint32_t a;
    asm("{ .reg .u64 t; cvta.to.shared.u64 t, %1; cvt.u32.u64 %0, t; }" : "=r"(a) : "l"(p));
    return a;
}
#define CP16(sa, gp)  asm volatile("cp.async.cg.shared.global [%0], [%1], 16;" :: "r"(sa), "l"(gp))
#define CP_COMMIT()   asm volatile("cp.async.commit_group;" ::: "memory")
#define CP_WAIT1()    asm volatile("cp.async.wait_group 1;" ::: "memory")
#define CP_WAIT0()    asm volatile("cp.async.wait_group 0;" ::: "memory")
#define LDSM4(r0, r1, r2, r3, a) \
    asm volatile("ldmatrix.sync.aligned.m8n8.x4.shared.b16 {%0,%1,%2,%3}, [%4];" \
        : "=r"(r0), "=r"(r1), "=r"(r2), "=r"(r3) : "r"(a))
#define LDSM2(r0, r1, a) \
    asm volatile("ldmatrix.sync.aligned.m8n8.x2.shared.b16 {%0,%1}, [%2];" \
        : "=r"(r0), "=r"(r1) : "r"(a))
#define MMA16816(d, a, bb2) \
    asm volatile("mma.sync.aligned.m16n8k16.row.col.f32.bf16.bf16.f32 " \
        "{%0,%1,%2,%3}, {%4,%5,%6,%7}, {%8,%9}, {%0,%1,%2,%3};" \
        : "+f"((d)[0]), "+f"((d)[1]), "+f"((d)[2]), "+f"((d)[3]) \
        : "r"((a)[0]), "r"((a)[1]), "r"((a)[2]), "r"((a)[3]), "r"((bb2)[0]), "r"((bb2)[1]))

__device__ __forceinline__ void st_split2(__nv_bfloat16* ph, __nv_bfloat16* pl, float v0, float v1) {
    __nv_bfloat162 hp, lp;
    hp.x = __float2bfloat16(v0); hp.y = __float2bfloat16(v1);
    lp.x = __float2bfloat16(v0 - __bfloat162float(hp.x));
    lp.y = __float2bfloat16(v1 - __bfloat162float(hp.y));
    *(__nv_bfloat162*)ph = hp;
    *(__nv_bfloat162*)pl = lp;
}

// ---------------- HMMA GEMM: D[128 M][128 N] tile = A(M,K) . B(N,K)^T, BK=64 ----------------
// EPI: 0 q/k (+bias[m], split) | 1 v (+bias[n], split) | 2 conv2 (relu+identity, f32+split)
//      3 qk (scale+relpos, f32) | 4 ao (scatter+residual, f32) | 5 ffn1 (relu+bias[n], split) | 6 ffn2 (f32)
constexpr int SMEMSZ = 131072;   // 2 stages x 4 parts x 16 KB (128x64 bf16, SW128)

template<int GATHER, int EPI>
__global__ void __launch_bounds__(256, 1) gemm_hm(
    const __nv_bfloat16* __restrict__ Ah, const __nv_bfloat16* __restrict__ Al,
    const __nv_bfloat16* __restrict__ Bh, const __nv_bfloat16* __restrict__ Bl,
    int K, int lda, int ldb, size_t sA, size_t sB,
    __nv_bfloat16* __restrict__ o0, __nv_bfloat16* __restrict__ o1, float* __restrict__ pF,
    int ldc, size_t sC,
    const float* __restrict__ bias, const float* __restrict__ r0,
    const float* __restrict__ r1, const float* __restrict__ r2)
{
    extern __shared__ __align__(128) char smraw[];
    const int tid = threadIdx.x, b = blockIdx.z;
    const int row0 = blockIdx.x * 128, col0 = blockIdx.y * 128;
    const uint32_t sbase = smem_u32(smraw);
    const int w = tid >> 5, lane = tid & 31;
    const int wm = w & 1, wn = w >> 1;          // warp tile: 64(m) x 32(n)

    Ah += (size_t)b * sA; Al += (size_t)b * sA;
    Bh += (size_t)b * sB; Bl += (size_t)b * sB;

    float acc[4][4][4];
    #pragma unroll
    for (int i = 0; i < 4; i++)
        #pragma unroll
        for (int j = 0; j < 4; j++)
            #pragma unroll
            for (int c = 0; c < 4; c++) acc[i][j][c] = 0.f;

    const int nC = K >> 6;

    auto load_stage = [&](int ci) {
        const uint32_t stg = (uint32_t)(ci & 1) * 65536u;
        int kk = 0, kh = 0, kw = 0, kbase = ci << 6;
        if (GATHER) { kk = ci / 36; kh = kk / 3; kw = kk - kh * 3; kbase = (ci - kk * 36) << 6; }
        #pragma unroll
        for (int i = 0; i < 4; i++) {
            int e = i * 256 + tid;
            int r = e >> 3, g = e & 7;
            uint32_t so = (uint32_t)(r * 128 + ((g ^ (r & 7)) << 4));
            size_t aoff;
            if (GATHER) {
                int p = row0 + r, ph = p / 48, pw = p - ph * 48;
                aoff = (size_t)((ph + kh) * 50 + pw + kw) * 2304 + kbase + g * 8;
            } else {
                aoff = (size_t)(row0 + r) * lda + kbase + g * 8;
            }
            CP16(sbase + stg + so,          Ah + aoff);
            CP16(sbase + stg + 16384 + so,  Al + aoff);
            size_t boff = (size_t)(col0 + r) * ldb + (ci << 6) + g * 8;
            CP16(sbase + stg + 32768 + so,  Bh + boff);
            CP16(sbase + stg + 49152 + so,  Bl + boff);
        }
    };

    auto compute_stage = [&](int ci) {
        const uint32_t sb = sbase + (uint32_t)(ci & 1) * 65536u;
        #pragma unroll
        for (int ks = 0; ks < 4; ks++) {
            uint32_t ah[4][4], al[4][4], bh[4][2], bl[4][2];
            const int ar = lane & 15, ac = lane >> 4;
            #pragma unroll
            for (int mi = 0; mi < 4; mi++) {
                int r = wm * 64 + mi * 16 + ar;
                int g = ks * 2 + ac;
                uint32_t off = (uint32_t)(r * 128 + ((g ^ (r & 7)) << 4));
                LDSM4(ah[mi][0], ah[mi][1], ah[mi][2], ah[mi][3], sb + off);
                LDSM4(al[mi][0], al[mi][1], al[mi][2], al[mi][3], sb + 16384 + off);
            }
            const int br = lane & 7, bc = (lane >> 3) & 1;
            #pragma unroll
            for (int ni = 0; ni < 4; ni++) {
                int r = wn * 32 + ni * 8 + br;
                int g = ks * 2 + bc;
                uint32_t off = (uint32_t)(r * 128 + ((g ^ (r & 7)) << 4));
                LDSM2(bh[ni][0], bh[ni][1], sb + 32768 + off);
                LDSM2(bl[ni][0], bl[ni][1], sb + 49152 + off);
            }
            #pragma unroll
            for (int mi = 0; mi < 4; mi++)
                #pragma unroll
                for (int ni = 0; ni < 4; ni++) {
                    MMA16816(acc[mi][ni], ah[mi], bh[ni]);
                    MMA16816(acc[mi][ni], ah[mi], bl[ni]);
                    MMA16816(acc[mi][ni], al[mi], bh[ni]);
                }
        }
    };

    load_stage(0); CP_COMMIT();
    #pragma unroll 1
    for (int ci = 0; ci < nC; ci++) {
        if (ci + 1 < nC) { load_stage(ci + 1); CP_COMMIT(); CP_WAIT1(); }
        else             { CP_WAIT0(); }
        __syncthreads();
        compute_stage(ci);
        __syncthreads();
    }

    // -------- epilogue --------
    const int lg = lane >> 2, lc = (lane & 3) * 2;
    #pragma unroll
    for (int mi = 0; mi < 4; mi++) {
        #pragma unroll
        for (int rr = 0; rr < 2; rr++) {
            const int gm = row0 + wm * 64 + mi * 16 + rr * 8 + lg;
            float rowb = 0.f, xv = 0.f;
            int ih = 0, iw = 0; size_t aorow = 0, resb = 0;
            if (EPI == 0) rowb = bias[gm];
            if (EPI == 2) xv = r2[(size_t)b * 2304 + gm];
            if (EPI == 3) { ih = gm / 48; iw = gm - ih * 48; }
            if (EPI == 4) {
                int bb = gm / 576, cc = (gm - bb * 576) * 4 + b;
                aorow = (size_t)bb * 2304 + cc;
                resb  = (size_t)bb * PLANE + cc;
            }
            #pragma unroll
            for (int ni = 0; ni < 4; ni++) {
                float v0 = acc[mi][ni][rr * 2 + 0];
                float v1 = acc[mi][ni][rr * 2 + 1];
                const int gn = col0 + wn * 32 + ni * 8 + lc;
                if (EPI == 0) { v0 += rowb; v1 += rowb; }
                else if (EPI == 1) { v0 += bias[gn]; v1 += bias[gn + 1]; }
                else if (EPI == 2) {
                    v0 = fmaxf(v0 + bias[gn]     + r0[gn]     * xv + r1[gn],     0.f);
                    v1 = fmaxf(v1 + bias[gn + 1] + r0[gn + 1] * xv + r1[gn + 1], 0.f);
                } else if (EPI == 3) {
                    int jh = gn / 48, jw = gn - jh * 48;   // gn, gn+1 same jh row (gn even, jw<=46)
                    int rbase = (ih - jh + 47) * 95 + (iw - jw + 47);
                    v0 = v0 * 0.0208333333333333f + bias[(rbase << 2) + b];
                    v1 = v1 * 0.0208333333333333f + bias[((rbase - 1) << 2) + b];
                } else if (EPI == 4) {
                    v0 += r0[resb + (size_t)gn * 2304];
                    v1 += r0[resb + (size_t)(gn + 1) * 2304];
                } else if (EPI == 5) {
                    v0 = fmaxf(v0 + bias[gn], 0.f);
                    v1 = fmaxf(v1 + bias[gn + 1], 0.f);
                } else if (EPI == 6) {
                    v0 += bias[gn]     + r0[(size_t)gm * ldc + gn];
                    v1 += bias[gn + 1] + r0[(size_t)gm * ldc + gn + 1];
                }
                size_t co = (size_t)gm * ldc + gn + (size_t)b * sC;
                if (EPI == 0 || EPI == 1 || EPI == 5) {
                    st_split2(o0 + co, o1 + co, v0, v1);
                } else if (EPI == 2) {
                    st_split2(o0 + co, o1 + co, v0, v1);
                    float2 f; f.x = v0; f.y = v1;
                    *(float2*)(pF + co) = f;
                } else if (EPI == 3 || EPI == 6) {
                    float2 f; f.x = v0; f.y = v1;
                    *(float2*)(pF + co) = f;
                } else if (EPI == 4) {
                    float2 f; f.x = v0; f.y = v1;
                    *(float2*)(pF + aorow * 2304 + gn) = f;
                }
            }
        }
    }
}

// ---------------- prep kernels ----------------
__global__ void conv1t_k(const float* __restrict__ x, const float* __restrict__ w1,
                         const float* __restrict__ b1)
{
    int idx = blockIdx.x * blockDim.x + threadIdx.x;
    if (idx >= Bsz * 2500 * 2304) return;
    int c = idx % 2304, t2 = idx / 2304, pp = t2 % 2500, b = t2 / 2500;
    int ph = pp / 50, pw = pp % 50;
    float v = 0.f;
    if (ph >= 1 && ph <= 48 && pw >= 1 && pw <= 48) {
        int h = ph - 1, ww = pw - 1;
        const float* xb = x + (size_t)b * 2304;
        const float* wc = w1 + (size_t)c * 9;
        float s = b1[c];
        #pragma unroll
        for (int kh = 0; kh < 3; kh++) {
            int hy = h + kh - 1;
            if (hy < 0 || hy >= 48) continue;
            #pragma unroll
            for (int kw = 0; kw < 3; kw++) {
                int wx = ww + kw - 1;
                if (wx < 0 || wx >= 48) continue;
                s += wc[kh*3+kw] * xb[hy*48 + wx];
            }
        }
        v = fmaxf(s, 0.f);
    }
    __nv_bfloat16 h16 = __float2bfloat16(v);
    gy_h[idx] = h16;
    gy_l[idx] = __float2bfloat16(v - __bfloat162float(h16));
}

__global__ void w2t_split_k(const float* __restrict__ w2)
{
    __shared__ float sm[2304];
    int base = blockIdx.x * 256, t = threadIdx.x;
    for (int i = t; i < 2304; i += 256) sm[i] = w2[(size_t)base * 9 + i];
    __syncthreads();
    int o = base / 2304, cin = (base % 2304) + t;
    #pragma unroll
    for (int kk = 0; kk < 9; kk++) {
        float v = sm[t * 9 + kk];
        size_t d = (size_t)o * KW2 + kk * 2304 + cin;
        __nv_bfloat16 h = __float2bfloat16(v);
        gw2_h[d] = h; gw2_l[d] = __float2bfloat16(v - __bfloat162float(h));
    }
}

__global__ void splitk(const float* __restrict__ s, __nv_bfloat16* __restrict__ h,
                       __nv_bfloat16* __restrict__ l, int n)
{
    int i = blockIdx.x * blockDim.x + threadIdx.x;
    if (i >= n) return;
    float v = s[i];
    __nv_bfloat16 hv = __float2bfloat16(v);
    h[i] = hv; l[i] = __float2bfloat16(v - __bfloat162float(hv));
}

__global__ void tsplit(const float* __restrict__ src, __nv_bfloat16* __restrict__ dh,
                       __nv_bfloat16* __restrict__ dl, int R, int Cl)
{
    __shared__ float t[32][33];
    int c0 = blockIdx.x * 32, r0 = blockIdx.y * 32;
    for (int i = threadIdx.y; i < 32; i += 8)
        t[i][threadIdx.x] = src[(size_t)(r0 + i) * Cl + c0 + threadIdx.x];
    __syncthreads();
    for (int i = threadIdx.y; i < 32; i += 8) {
        float v = t[threadIdx.x][i];
        size_t d = (size_t)(c0 + i) * R + r0 + threadIdx.x;
        __nv_bfloat16 h = __float2bfloat16(v);
        dh[d] = h; dl[d] = __float2bfloat16(v - __bfloat162float(h));
    }
}

__global__ void softmax_split_k()
{
    size_t row = blockIdx.x;
    float* p = gqk + row * 2304;
    int t = threadIdx.x;
    float v[9], mx = -1e30f;
    #pragma unroll
    for (int i = 0; i < 9; i++) { v[i] = p[t + i*256]; mx = fmaxf(mx, v[i]); }
    __shared__ float red[256];
    red[t] = mx; __syncthreads();
    for (int s = 128; s > 0; s >>= 1) { if (t < s) red[t] = fmaxf(red[t], red[t+s]); __syncthreads(); }
    mx = red[0]; __syncthreads();
    float sum = 0.f;
    #pragma unroll
    for (int i = 0; i < 9; i++) { v[i] = __expf(v[i] - mx); sum += v[i]; }
    red[t] = sum; __syncthreads();
    for (int s = 128; s > 0; s >>= 1) { if (t < s) red[t] += red[t+s]; __syncthreads(); }
    float inv = 1.0f / red[0];
    #pragma unroll
    for (int i = 0; i < 9; i++) {
        float r = v[i] * inv;
        size_t d = row * 2304 + t + i*256;
        __nv_bfloat16 h = __float2bfloat16(r);
        gat_h[d] = h; gat_l[d] = __float2bfloat16(r - __bfloat162float(h));
    }
}

template<bool SPLIT>
__global__ void ln_k(const float* __restrict__ in, float* __restrict__ out,
                     __nv_bfloat16* __restrict__ oh, __nv_bfloat16* __restrict__ ol,
                     const float* __restrict__ gam, const float* __restrict__ bet)
{
    size_t row = blockIdx.x;
    const float* p = in + row * Ee;
    int t = threadIdx.x;
    float v[9], s = 0.f;
    #pragma unroll
    for (int i = 0; i < 9; i++) { v[i] = p[t + i*256]; s += v[i]; }
    __shared__ float red[256];
    red[t] = s; __syncthreads();
    for (int st = 128; st > 0; st >>= 1) { if (t < st) red[t] += red[t+st]; __syncthreads(); }
    float mu = red[0] * (1.f / 2304.f); __syncthreads();
    float s2 = 0.f;
    #pragma unroll
    for (int i = 0; i < 9; i++) { float d = v[i] - mu; s2 += d * d; }
    red[t] = s2; __syncthreads();
    for (int st = 128; st > 0; st >>= 1) { if (t < st) red[t] += red[t+st]; __syncthreads(); }
    float rs = rsqrtf(red[0] * (1.f / 2304.f) + 1e-5f);
    #pragma unroll
    for (int i = 0; i < 9; i++) {
        int n = t + i*256;
        float r = (v[i] - mu) * rs * gam[n] + bet[n];
        out[row * Ee + n] = r;
        if (SPLIT) {
            __nv_bfloat16 h = __float2bfloat16(r);
            oh[row * Ee + n] = h; ol[row * Ee + n] = __float2bfloat16(r - __bfloat162float(h));
        }
    }
}

__global__ void maxpool_k(const float* __restrict__ in, float* __restrict__ out)
{
    int idx = blockIdx.x * blockDim.x + threadIdx.x;
    if (idx >= Bsz * Cc * 576) return;
    int r = idx % 576, bc = idx / 576, i = r / 24, j = r % 24;
    const float* pp = in + (size_t)bc * 2304 + (2*i) * 48 + 2*j;
    out[idx] = fmaxf(fmaxf(pp[0], pp[1]), fmaxf(pp[48], pp[49]));
}

// ---------------- launch ----------------
#define GAB(v, sym) __nv_bfloat16* v; { void* _p; cudaGetSymbolAddress(&_p, sym); v = (__nv_bfloat16*)_p; }
#define GAF(v, sym) float* v;         { void* _p; cudaGetSymbolAddress(&_p, sym); v = (float*)_p; }

extern "C" void kernel_launch(void* const* d_in, const int* in_sizes, int n_in,
                              void* d_out, int out_size)
{
    (void)in_sizes; (void)n_in; (void)out_size;
    const float* x       = (const float*)d_in[0];
    const float* conv1_w = (const float*)d_in[1];
    const float* conv1_b = (const float*)d_in[2];
    const float* conv2_w = (const float*)d_in[3];
    const float* conv2_b = (const float*)d_in[4];
    const float* id_w    = (const float*)d_in[5];
    const float* id_b    = (const float*)d_in[6];
    const float* q_w     = (const float*)d_in[7];
    const float* q_b     = (const float*)d_in[8];
    const float* k_w     = (const float*)d_in[9];
    const float* k_b     = (const float*)d_in[10];
    const float* v_w     = (const float*)d_in[11];
    const float* v_b     = (const float*)d_in[12];
    const float* rel_tab = (const float*)d_in[13];
    const float* ln1_g   = (const float*)d_in[14];
    const float* ln1_b   = (const float*)d_in[15];
    const float* ln2_g   = (const float*)d_in[16];
    const float* ln2_b   = (const float*)d_in[17];
    const float* ffn_w1  = (const float*)d_in[18];
    const float* ffn_b1  = (const float*)d_in[19];
    const float* ffn_w2  = (const float*)d_in[20];
    const float* ffn_b2  = (const float*)d_in[21];
    float* out  = (float*)d_out;
    float* pout = out + (size_t)Bsz * Cc * Np;

    GAB(py_h, gy_h)   GAB(py_l, gy_l)
    GAB(pw2h, gw2_h)  GAB(pw2l, gw2_l)
    GAB(pqwh, gqw_h)  GAB(pqwl, gqw_l)
    GAB(pkwh, gkw_h)  GAB(pkwl, gkw_l)
    GAB(pvwh, gvw_h)  GAB(pvwl, gvw_l)
    GAB(pw1h, gw1t_h) GAB(pw1l, gw1t_l)
    GAB(pw2fh, gw2f_h) GAB(pw2fl, gw2f_l)
    GAF(pdw, gdown)   GAB(pdth, gdt_h)  GAB(pdtl, gdt_l)
    GAB(pqh, gq_h)    GAB(pql, gq_l)
    GAB(pkh, gk_h)    GAB(pkl, gk_l)
    GAB(pvh, gv_h)    GAB(pvl, gv_l)
    GAF(pqk, gqk)
    GAB(path, gat_h)  GAB(patl, gat_l)
    GAF(ph1p, gh1p)   GAF(ph1, gh1)
    GAB(ph1h, gh1_h)  GAB(ph1l, gh1_l)
    GAB(pfh, gf_h)    GAB(pfl, gf_l)

    cudaFuncSetAttribute(gemm_hm<1,2>, cudaFuncAttributeMaxDynamicSharedMemorySize, SMEMSZ);
    cudaFuncSetAttribute(gemm_hm<0,0>, cudaFuncAttributeMaxDynamicSharedMemorySize, SMEMSZ);
    cudaFuncSetAttribute(gemm_hm<0,1>, cudaFuncAttributeMaxDynamicSharedMemorySize, SMEMSZ);
    cudaFuncSetAttribute(gemm_hm<0,3>, cudaFuncAttributeMaxDynamicSharedMemorySize, SMEMSZ);
    cudaFuncSetAttribute(gemm_hm<0,4>, cudaFuncAttributeMaxDynamicSharedMemorySize, SMEMSZ);
    cudaFuncSetAttribute(gemm_hm<0,5>, cudaFuncAttributeMaxDynamicSharedMemorySize, SMEMSZ);
    cudaFuncSetAttribute(gemm_hm<0,6>, cudaFuncAttributeMaxDynamicSharedMemorySize, SMEMSZ);

    // prep
    conv1t_k<<<(Bsz*2500*2304 + 255)/256, 256>>>(x, conv1_w, conv1_b);
    w2t_split_k<<<2304*2304/256, 256>>>(conv2_w);
    splitk<<<(2304*2304 + 255)/256, 256>>>(q_w, pqwh, pqwl, 2304*2304);
    splitk<<<(2304*2304 + 255)/256, 256>>>(k_w, pkwh, pkwl, 2304*2304);
    splitk<<<(2304*2304 + 255)/256, 256>>>(v_w, pvwh, pvwl, 2304*2304);
    tsplit<<<dim3(E2/32, Ee/32), dim3(32,8)>>>(ffn_w1, pw1h, pw1l, Ee, E2);   // w1t [4608][2304]
    tsplit<<<dim3(Ee/32, E2/32), dim3(32,8)>>>(ffn_w2, pw2fh, pw2fl, E2, Ee); // w2ft [2304][4608]

    // conv2 implicit GEMM: down^T[p][o]  (A = im2col(y1) gathered, B = w2t rows o)
    gemm_hm<1,2><<<dim3(18,18,Bsz), 256, SMEMSZ>>>(py_h, py_l, pw2h, pw2l,
        KW2, 2304, KW2, (size_t)2500*2304, 0, pdth, pdtl, pdw, 2304, PLANE,
        conv2_b, id_w, id_b, x);
    // q, k: D[e][p] = qw . down^T
    gemm_hm<0,0><<<dim3(18,18,Bsz), 256, SMEMSZ>>>(pqwh, pqwl, pdth, pdtl,
        2304, 2304, 2304, 0, PLANE, pqh, pql, nullptr, 2304, PLANE, q_b, nullptr, nullptr, nullptr);
    gemm_hm<0,0><<<dim3(18,18,Bsz), 256, SMEMSZ>>>(pkwh, pkwl, pdth, pdtl,
        2304, 2304, 2304, 0, PLANE, pkh, pkl, nullptr, 2304, PLANE, k_b, nullptr, nullptr, nullptr);
    // v^T: D[p][e] = down^T . vw
    gemm_hm<0,1><<<dim3(18,18,Bsz), 256, SMEMSZ>>>(pdth, pdtl, pvwh, pvwl,
        2304, 2304, 2304, PLANE, 0, pvh, pvl, nullptr, 2304, PLANE, v_b, nullptr, nullptr, nullptr);
    // qk = q.k^T/48 + relpos
    gemm_hm<0,3><<<dim3(18,18,Bsz), 256, SMEMSZ>>>(pqh, pql, pkh, pkl,
        2304, 2304, 2304, PLANE, PLANE, nullptr, nullptr, pqk, 2304, PLANE,
        rel_tab, nullptr, nullptr, nullptr);
    softmax_split_k<<<Bsz*Ee, 256>>>();
    // ao scatter + residual
    gemm_hm<0,4><<<dim3(18,18,Bsz), 256, SMEMSZ>>>(path, patl, pvh, pvl,
        2304, 2304, 2304, PLANE, PLANE, nullptr, nullptr, ph1p, 2304, 0,
        nullptr, pdw, nullptr, nullptr);
    ln_k<true><<<Bsz*Cc, 256>>>(ph1p, ph1, ph1h, ph1l, ln1_g, ln1_b);
    // ffn1: [9216][2304] x w1t -> [9216][4608]
    gemm_hm<0,5><<<dim3(72,36,1), 256, SMEMSZ>>>(ph1h, ph1l, pw1h, pw1l,
        2304, 2304, 2304, 0, 0, pfh, pfl, nullptr, E2, 0, ffn_b1, nullptr, nullptr, nullptr);
    // ffn2 + residual -> d_out (pre-LN2)
    gemm_hm<0,6><<<dim3(72,18,1), 256, SMEMSZ>>>(pfh, pfl, pw2fh, pw2fl,
        E2, E2, E2, 0, 0, nullptr, nullptr, out, 2304, 0, ffn_b2, ph1, nullptr, nullptr);
    ln_k<false><<<Bsz*Cc, 256>>>(out, out, nullptr, nullptr, ln2_g, ln2_b);
    maxpool_k<<<(Bsz*Cc*576 + 255)/256, 256>>>(out, pout);
}

// round 8
// speedup vs baseline: 4.8255x; 1.3525x over previous
#include <cuda_runtime.h>
#include <cuda_bf16.h>
#include <cstdint>

constexpr int Bsz = 4, Np = 2304, Cc = 2304, Ee = 2304, E2 = 4608;
constexpr size_t PLANE = (size_t)Np * Cc;

// ---------------- scratch ----------------
__device__ float         gy_f[(size_t)Bsz*2500*2304];               // relu(conv1), padded 50x50, channel-last
__device__ __nv_bfloat16 gV_h[(size_t)16*PLANE], gV_l[(size_t)16*PLANE];   // Winograd input transform
__device__ __nv_bfloat16 gU_h[(size_t)16*PLANE], gU_l[(size_t)16*PLANE];   // Winograd weight transform
__device__ float         gM  [(size_t)16*PLANE];                    // Winograd products
__device__ __nv_bfloat16 gqw_h[(size_t)2304*2304],    gqw_l[(size_t)2304*2304];
__device__ __nv_bfloat16 gkw_h[(size_t)2304*2304],    gkw_l[(size_t)2304*2304];
__device__ __nv_bfloat16 gvw_h[(size_t)2304*2304],    gvw_l[(size_t)2304*2304];
__device__ __nv_bfloat16 gw1t_h[(size_t)E2*Ee],       gw1t_l[(size_t)E2*Ee];
__device__ __nv_bfloat16 gw2f_h[(size_t)Ee*E2],       gw2f_l[(size_t)Ee*E2];
__device__ float         gdown[(size_t)Bsz*PLANE];                  // down^T fp32 [b][p][o]
__device__ __nv_bfloat16 gdt_h[(size_t)Bsz*PLANE],  gdt_l[(size_t)Bsz*PLANE];
__device__ __nv_bfloat16 gq_h[(size_t)Bsz*PLANE],   gq_l[(size_t)Bsz*PLANE];
__device__ __nv_bfloat16 gk_h[(size_t)Bsz*PLANE],   gk_l[(size_t)Bsz*PLANE];
__device__ __nv_bfloat16 gv_h[(size_t)Bsz*PLANE],   gv_l[(size_t)Bsz*PLANE];  // v^T [b][p][e]
__device__ float         gqk[(size_t)Bsz*PLANE];
__device__ __nv_bfloat16 gat_h[(size_t)Bsz*PLANE],  gat_l[(size_t)Bsz*PLANE];
__device__ float         gh1p[(size_t)Bsz*PLANE],   gh1[(size_t)Bsz*PLANE];
__device__ __nv_bfloat16 gh1_h[(size_t)Bsz*PLANE],  gh1_l[(size_t)Bsz*PLANE];
__device__ __nv_bfloat16 gf_h[(size_t)9216*E2],     gf_l[(size_t)9216*E2];

// ---------------- PTX helpers ----------------
__device__ __forceinline__ uint32_t smem_u32(const void* p) {
    uint32_t a;
    asm("{ .reg .u64 t; cvta.to.shared.u64 t, %1; cvt.u32.u64 %0, t; }" : "=r"(a) : "l"(p));
    return a;
}
#define CP16(sa, gp)  asm volatile("cp.async.cg.shared.global [%0], [%1], 16;" :: "r"(sa), "l"(gp))
#define CP_COMMIT()   asm volatile("cp.async.commit_group;" ::: "memory")
#define CP_WAIT1()    asm volatile("cp.async.wait_group 1;" ::: "memory")
#define CP_WAIT0()    asm volatile("cp.async.wait_group 0;" ::: "memory")
#define LDSM4(r0, r1, r2, r3, a) \
    asm volatile("ldmatrix.sync.aligned.m8n8.x4.shared.b16 {%0,%1,%2,%3}, [%4];" \
        : "=r"(r0), "=r"(r1), "=r"(r2), "=r"(r3) : "r"(a))
#define LDSM2(r0, r1, a) \
    asm volatile("ldmatrix.sync.aligned.m8n8.x2.shared.b16 {%0,%1}, [%2];" \
        : "=r"(r0), "=r"(r1) : "r"(a))
#define MMA16816(d, a, bb2) \
    asm volatile("mma.sync.aligned.m16n8k16.row.col.f32.bf16.bf16.f32 " \
        "{%0,%1,%2,%3}, {%4,%5,%6,%7}, {%8,%9}, {%0,%1,%2,%3};" \
        : "+f"((d)[0]), "+f"((d)[1]), "+f"((d)[2]), "+f"((d)[3]) \
        : "r"((a)[0]), "r"((a)[1]), "r"((a)[2]), "r"((a)[3]), "r"((bb2)[0]), "r"((bb2)[1]))

__device__ __forceinline__ void st_split2(__nv_bfloat16* ph, __nv_bfloat16* pl, float v0, float v1) {
    __nv_bfloat162 hp, lp;
    hp.x = __float2bfloat16(v0); hp.y = __float2bfloat16(v1);
    lp.x = __float2bfloat16(v0 - __bfloat162float(hp.x));
    lp.y = __float2bfloat16(v1 - __bfloat162float(hp.y));
    *(__nv_bfloat162*)ph = hp;
    *(__nv_bfloat162*)pl = lp;
}
__device__ __forceinline__ void split1(float v, __nv_bfloat16* ph, __nv_bfloat16* pl) {
    __nv_bfloat16 h = __float2bfloat16(v);
    *ph = h; *pl = __float2bfloat16(v - __bfloat162float(h));
}

// ---------------- HMMA GEMM: D[128 M][128 N] tile = A(M,K) . B(N,K)^T, BK=64 ----------------
// EPI: 0 q/k (+bias[m], split) | 1 v (+bias[n], split) | 3 qk (scale+relpos, f32)
//      4 ao (scatter+residual, f32) | 5 ffn1 (relu+bias[n], split) | 6 ffn2 (f32+bias+res) | 7 raw f32
constexpr int SMEMSZ = 131072;

template<int EPI>
__global__ void __launch_bounds__(256, 1) gemm_hm(
    const __nv_bfloat16* __restrict__ Ah, const __nv_bfloat16* __restrict__ Al,
    const __nv_bfloat16* __restrict__ Bh, const __nv_bfloat16* __restrict__ Bl,
    int K, int lda, int ldb, size_t sA, size_t sB,
    __nv_bfloat16* __restrict__ o0, __nv_bfloat16* __restrict__ o1, float* __restrict__ pF,
    int ldc, size_t sC,
    const float* __restrict__ bias, const float* __restrict__ r0)
{
    extern __shared__ __align__(128) char smraw[];
    const int tid = threadIdx.x, b = blockIdx.z;
    const int row0 = blockIdx.x * 128, col0 = blockIdx.y * 128;
    const uint32_t sbase = smem_u32(smraw);
    const int w = tid >> 5, lane = tid & 31;
    const int wm = w & 1, wn = w >> 1;          // warp tile: 64(m) x 32(n)

    Ah += (size_t)b * sA; Al += (size_t)b * sA;
    Bh += (size_t)b * sB; Bl += (size_t)b * sB;

    float acc[4][4][4];
    #pragma unroll
    for (int i = 0; i < 4; i++)
        #pragma unroll
        for (int j = 0; j < 4; j++)
            #pragma unroll
            for (int c = 0; c < 4; c++) acc[i][j][c] = 0.f;

    const int nC = K >> 6;

    auto load_stage = [&](int ci) {
        const uint32_t stg = (uint32_t)(ci & 1) * 65536u;
        const int kbase = ci << 6;
        #pragma unroll
        for (int i = 0; i < 4; i++) {
            int e = i * 256 + tid;
            int r = e >> 3, g = e & 7;
            uint32_t so = (uint32_t)(r * 128 + ((g ^ (r & 7)) << 4));
            size_t aoff = (size_t)(row0 + r) * lda + kbase + g * 8;
            CP16(sbase + stg + so,          Ah + aoff);
            CP16(sbase + stg + 16384 + so,  Al + aoff);
            size_t boff = (size_t)(col0 + r) * ldb + kbase + g * 8;
            CP16(sbase + stg + 32768 + so,  Bh + boff);
            CP16(sbase + stg + 49152 + so,  Bl + boff);
        }
    };

    auto compute_stage = [&](int ci) {
        const uint32_t sb = sbase + (uint32_t)(ci & 1) * 65536u;
        #pragma unroll
        for (int ks = 0; ks < 4; ks++) {
            uint32_t ah[4][4], al[4][4], bh[4][2], bl[4][2];
            const int ar = lane & 15, ac = lane >> 4;
            #pragma unroll
            for (int mi = 0; mi < 4; mi++) {
                int r = wm * 64 + mi * 16 + ar;
                int g = ks * 2 + ac;
                uint32_t off = (uint32_t)(r * 128 + ((g ^ (r & 7)) << 4));
                LDSM4(ah[mi][0], ah[mi][1], ah[mi][2], ah[mi][3], sb + off);
                LDSM4(al[mi][0], al[mi][1], al[mi][2], al[mi][3], sb + 16384 + off);
            }
            const int br = lane & 7, bc = (lane >> 3) & 1;
            #pragma unroll
            for (int ni = 0; ni < 4; ni++) {
                int r = wn * 32 + ni * 8 + br;
                int g = ks * 2 + bc;
                uint32_t off = (uint32_t)(r * 128 + ((g ^ (r & 7)) << 4));
                LDSM2(bh[ni][0], bh[ni][1], sb + 32768 + off);
                LDSM2(bl[ni][0], bl[ni][1], sb + 49152 + off);
            }
            #pragma unroll
            for (int mi = 0; mi < 4; mi++)
                #pragma unroll
                for (int ni = 0; ni < 4; ni++) {
                    MMA16816(acc[mi][ni], ah[mi], bh[ni]);
                    MMA16816(acc[mi][ni], ah[mi], bl[ni]);
                    MMA16816(acc[mi][ni], al[mi], bh[ni]);
                }
        }
    };

    load_stage(0); CP_COMMIT();
    #pragma unroll 1
    for (int ci = 0; ci < nC; ci++) {
        if (ci + 1 < nC) { load_stage(ci + 1); CP_COMMIT(); CP_WAIT1(); }
        else             { CP_WAIT0(); }
        __syncthreads();
        compute_stage(ci);
        __syncthreads();
    }

    // -------- epilogue --------
    const int lg = lane >> 2, lc = (lane & 3) * 2;
    #pragma unroll
    for (int mi = 0; mi < 4; mi++) {
        #pragma unroll
        for (int rr = 0; rr < 2; rr++) {
            const int gm = row0 + wm * 64 + mi * 16 + rr * 8 + lg;
            float rowb = 0.f;
            int ih = 0, iw = 0; size_t aorow = 0, resb = 0;
            if (EPI == 0) rowb = bias[gm];
            if (EPI == 3) { ih = gm / 48; iw = gm - ih * 48; }
            if (EPI == 4) {
                int bb = gm / 576, cc = (gm - bb * 576) * 4 + b;
                aorow = (size_t)bb * 2304 + cc;
                resb  = (size_t)bb * PLANE + cc;
            }
            #pragma unroll
            for (int ni = 0; ni < 4; ni++) {
                float v0 = acc[mi][ni][rr * 2 + 0];
                float v1 = acc[mi][ni][rr * 2 + 1];
                const int gn = col0 + wn * 32 + ni * 8 + lc;
                if (EPI == 0) { v0 += rowb; v1 += rowb; }
                else if (EPI == 1) { v0 += bias[gn]; v1 += bias[gn + 1]; }
                else if (EPI == 3) {
                    int jh = gn / 48, jw = gn - jh * 48;
                    int rbase = (ih - jh + 47) * 95 + (iw - jw + 47);
                    v0 = v0 * 0.0208333333333333f + bias[(rbase << 2) + b];
                    v1 = v1 * 0.0208333333333333f + bias[((rbase - 1) << 2) + b];
                } else if (EPI == 4) {
                    v0 += r0[resb + (size_t)gn * 2304];
                    v1 += r0[resb + (size_t)(gn + 1) * 2304];
                } else if (EPI == 5) {
                    v0 = fmaxf(v0 + bias[gn], 0.f);
                    v1 = fmaxf(v1 + bias[gn + 1], 0.f);
                } else if (EPI == 6) {
                    v0 += bias[gn]     + r0[(size_t)gm * ldc + gn];
                    v1 += bias[gn + 1] + r0[(size_t)gm * ldc + gn + 1];
                }
                size_t co = (size_t)gm * ldc + gn + (size_t)b * sC;
                if (EPI == 0 || EPI == 1 || EPI == 5) {
                    st_split2(o0 + co, o1 + co, v0, v1);
                } else if (EPI == 3 || EPI == 6 || EPI == 7) {
                    float2 f; f.x = v0; f.y = v1;
                    *(float2*)(pF + co) = f;
                } else if (EPI == 4) {
                    float2 f; f.x = v0; f.y = v1;
                    *(float2*)(pF + aorow * 2304 + gn) = f;
                }
            }
        }
    }
}

// ---------------- conv1 (CIN=1) + ReLU -> padded fp32, channel-last ----------------
__global__ void conv1f_k(const float* __restrict__ x, const float* __restrict__ w1,
                         const float* __restrict__ b1)
{
    int idx = blockIdx.x * blockDim.x + threadIdx.x;
    if (idx >= Bsz * 2500 * 2304) return;
    int c = idx % 2304, t2 = idx / 2304, pp = t2 % 2500, b = t2 / 2500;
    int ph = pp / 50, pw = pp % 50;
    float v = 0.f;
    if (ph >= 1 && ph <= 48 && pw >= 1 && pw <= 48) {
        int h = ph - 1, ww = pw - 1;
        const float* xb = x + (size_t)b * 2304;
        const float* wc = w1 + (size_t)c * 9;
        float s = b1[c];
        #pragma unroll
        for (int kh = 0; kh < 3; kh++) {
            int hy = h + kh - 1;
            if (hy < 0 || hy >= 48) continue;
            #pragma unroll
            for (int kw = 0; kw < 3; kw++) {
                int wx = ww + kw - 1;
                if (wx < 0 || wx >= 48) continue;
                s += wc[kh*3+kw] * xb[hy*48 + wx];
            }
        }
        v = fmaxf(s, 0.f);
    }
    gy_f[idx] = v;
}

// ---------------- Winograd weight transform: U = G g G^T, split -> gU[xi][cout][cin] ----------------
__global__ void u_trans_k(const float* __restrict__ w2)
{
    int idx = blockIdx.x * blockDim.x + threadIdx.x;
    if (idx >= 2304 * 2304) return;
    int cin = idx % 2304, cout = idx / 2304;
    const float* g = w2 + (size_t)idx * 9;
    float gw[4][3];
    #pragma unroll
    for (int j = 0; j < 3; j++) {
        gw[0][j] = g[j];
        gw[1][j] = 0.5f * (g[j] + g[3 + j] + g[6 + j]);
        gw[2][j] = 0.5f * (g[j] - g[3 + j] + g[6 + j]);
        gw[3][j] = g[6 + j];
    }
    size_t base = (size_t)cout * 2304 + cin;
    #pragma unroll
    for (int i = 0; i < 4; i++) {
        float u0 = gw[i][0];
        float u1 = 0.5f * (gw[i][0] + gw[i][1] + gw[i][2]);
        float u2 = 0.5f * (gw[i][0] - gw[i][1] + gw[i][2]);
        float u3 = gw[i][2];
        float uu[4] = {u0, u1, u2, u3};
        #pragma unroll
        for (int j = 0; j < 4; j++) {
            size_t d = (size_t)(i * 4 + j) * PLANE + base;
            split1(uu[j], &gU_h[d], &gU_l[d]);
        }
    }
}

// ---------------- Winograd input transform: V = B^T d B, split -> gV[xi][t][cin] ----------------
__global__ void v_trans_k()
{
    int idx = blockIdx.x * blockDim.x + threadIdx.x;
    if (idx >= Bsz * 576 * 2304) return;
    int cin = idx % 2304, r2 = idx / 2304, tile = r2 % 576, b = r2 / 576;
    int ty = tile / 24, tx = tile % 24;
    const float* base = gy_f + ((size_t)b * 2500 + (2 * ty) * 50 + 2 * tx) * 2304 + cin;
    float d[4][4];
    #pragma unroll
    for (int r = 0; r < 4; r++)
        #pragma unroll
        for (int c = 0; c < 4; c++)
            d[r][c] = base[((size_t)r * 50 + c) * 2304];
    float t[4][4];
    #pragma unroll
    for (int j = 0; j < 4; j++) {
        t[0][j] = d[0][j] - d[2][j];
        t[1][j] = d[1][j] + d[2][j];
        t[2][j] = d[2][j] - d[1][j];
        t[3][j] = d[1][j] - d[3][j];
    }
    size_t obase = ((size_t)b * 576 + tile) * 2304 + cin;
    #pragma unroll
    for (int i = 0; i < 4; i++) {
        float v0 = t[i][0] - t[i][2];
        float v1 = t[i][1] + t[i][2];
        float v2 = t[i][2] - t[i][1];
        float v3 = t[i][1] - t[i][3];
        float vv[4] = {v0, v1, v2, v3};
        #pragma unroll
        for (int j = 0; j < 4; j++) {
            size_t dd = (size_t)(i * 4 + j) * PLANE + obase;
            split1(vv[j], &gV_h[dd], &gV_l[dd]);
        }
    }
}

// ---------------- Winograd inverse: Y = A^T m A, + bias + identity + relu -> down^T ----------------
__global__ void winv_k(const float* __restrict__ x, const float* __restrict__ c2b,
                       const float* __restrict__ idw, const float* __restrict__ idb)
{
    int idx = blockIdx.x * blockDim.x + threadIdx.x;
    if (idx >= Bsz * 576 * 2304) return;
    int cout = idx % 2304, r2 = idx / 2304, tile = r2 % 576, b = r2 / 576;
    size_t mbase = ((size_t)b * 576 + tile) * 2304 + cout;
    float m[4][4];
    #pragma unroll
    for (int xi = 0; xi < 16; xi++)
        m[xi >> 2][xi & 3] = gM[(size_t)xi * PLANE + mbase];
    float s[2][4];
    #pragma unroll
    for (int j = 0; j < 4; j++) {
        s[0][j] = m[0][j] + m[1][j] + m[2][j];
        s[1][j] = m[1][j] - m[2][j] - m[3][j];
    }
    float y[2][2];
    #pragma unroll
    for (int i = 0; i < 2; i++) {
        y[i][0] = s[i][0] + s[i][1] + s[i][2];
        y[i][1] = s[i][1] - s[i][2] - s[i][3];
    }
    int ty = tile / 24, tx = tile % 24;
    int p00 = (2 * ty) * 48 + 2 * tx;
    float cb = c2b[cout], iw = idw[cout], ib = idb[cout];
    const float* xb = x + (size_t)b * 2304;
    #pragma unroll
    for (int dy = 0; dy < 2; dy++)
        #pragma unroll
        for (int dx = 0; dx < 2; dx++) {
            int p = p00 + dy * 48 + dx;
            float v = fmaxf(y[dy][dx] + cb + iw * xb[p] + ib, 0.f);
            size_t o = (size_t)b * PLANE + (size_t)p * 2304 + cout;
            gdown[o] = v;
            split1(v, &gdt_h[o], &gdt_l[o]);
        }
}

// ---------------- other prep kernels ----------------
__global__ void splitk(const float* __restrict__ s, __nv_bfloat16* __restrict__ h,
                       __nv_bfloat16* __restrict__ l, int n)
{
    int i = blockIdx.x * blockDim.x + threadIdx.x;
    if (i >= n) return;
    split1(s[i], h + i, l + i);
}

__global__ void tsplit(const float* __restrict__ src, __nv_bfloat16* __restrict__ dh,
                       __nv_bfloat16* __restrict__ dl, int R, int Cl)
{
    __shared__ float t[32][33];
    int c0 = blockIdx.x * 32, r0 = blockIdx.y * 32;
    for (int i = threadIdx.y; i < 32; i += 8)
        t[i][threadIdx.x] = src[(size_t)(r0 + i) * Cl + c0 + threadIdx.x];
    __syncthreads();
    for (int i = threadIdx.y; i < 32; i += 8) {
        float v = t[threadIdx.x][i];
        size_t d = (size_t)(c0 + i) * R + r0 + threadIdx.x;
        split1(v, &dh[d], &dl[d]);
    }
}

__global__ void softmax_split_k()
{
    size_t row = blockIdx.x;
    float* p = gqk + row * 2304;
    int t = threadIdx.x;
    float v[9], mx = -1e30f;
    #pragma unroll
    for (int i = 0; i < 9; i++) { v[i] = p[t + i*256]; mx = fmaxf(mx, v[i]); }
    __shared__ float red[256];
    red[t] = mx; __syncthreads();
    for (int s = 128; s > 0; s >>= 1) { if (t < s) red[t] = fmaxf(red[t], red[t+s]); __syncthreads(); }
    mx = red[0]; __syncthreads();
    float sum = 0.f;
    #pragma unroll
    for (int i = 0; i < 9; i++) { v[i] = __expf(v[i] - mx); sum += v[i]; }
    red[t] = sum; __syncthreads();
    for (int s = 128; s > 0; s >>= 1) { if (t < s) red[t] += red[t+s]; __syncthreads(); }
    float inv = 1.0f / red[0];
    #pragma unroll
    for (int i = 0; i < 9; i++) {
        size_t d = row * 2304 + t + i*256;
        split1(v[i] * inv, &gat_h[d], &gat_l[d]);
    }
}

template<bool SPLIT>
__global__ void ln_k(const float* __restrict__ in, float* __restrict__ out,
                     __nv_bfloat16* __restrict__ oh, __nv_bfloat16* __restrict__ ol,
                     const float* __restrict__ gam, const float* __restrict__ bet)
{
    size_t row = blockIdx.x;
    const float* p = in + row * Ee;
    int t = threadIdx.x;
    float v[9], s = 0.f;
    #pragma unroll
    for (int i = 0; i < 9; i++) { v[i] = p[t + i*256]; s += v[i]; }
    __shared__ float red[256];
    red[t] = s; __syncthreads();
    for (int st = 128; st > 0; st >>= 1) { if (t < st) red[t] += red[t+st]; __syncthreads(); }
    float mu = red[0] * (1.f / 2304.f); __syncthreads();
    float s2 = 0.f;
    #pragma unroll
    for (int i = 0; i < 9; i++) { float d = v[i] - mu; s2 += d * d; }
    red[t] = s2; __syncthreads();
    for (int st = 128; st > 0; st >>= 1) { if (t < st) red[t] += red[t+st]; __syncthreads(); }
    float rs = rsqrtf(red[0] * (1.f / 2304.f) + 1e-5f);
    #pragma unroll
    for (int i = 0; i < 9; i++) {
        int n = t + i*256;
        float r = (v[i] - mu) * rs * gam[n] + bet[n];
        out[row * Ee + n] = r;
        if (SPLIT) split1(r, &oh[row * Ee + n], &ol[row * Ee + n]);
    }
}

__global__ void maxpool_k(const float* __restrict__ in, float* __restrict__ out)
{
    int idx = blockIdx.x * blockDim.x + threadIdx.x;
    if (idx >= Bsz * Cc * 576) return;
    int r = idx % 576, bc = idx / 576, i = r / 24, j = r % 24;
    const float* pp = in + (size_t)bc * 2304 + (2*i) * 48 + 2*j;
    out[idx] = fmaxf(fmaxf(pp[0], pp[1]), fmaxf(pp[48], pp[49]));
}

// ---------------- launch ----------------
#define GAB(v, sym) __nv_bfloat16* v; { void* _p; cudaGetSymbolAddress(&_p, sym); v = (__nv_bfloat16*)_p; }
#define GAF(v, sym) float* v;         { void* _p; cudaGetSymbolAddress(&_p, sym); v = (float*)_p; }

extern "C" void kernel_launch(void* const* d_in, const int* in_sizes, int n_in,
                              void* d_out, int out_size)
{
    (void)in_sizes; (void)n_in; (void)out_size;
    const float* x       = (const float*)d_in[0];
    const float* conv1_w = (const float*)d_in[1];
    const float* conv1_b = (const float*)d_in[2];
    const float* conv2_w = (const float*)d_in[3];
    const float* conv2_b = (const float*)d_in[4];
    const float* id_w    = (const float*)d_in[5];
    const float* id_b    = (const float*)d_in[6];
    const float* q_w     = (const float*)d_in[7];
    const float* q_b     = (const float*)d_in[8];
    const float* k_w     = (const float*)d_in[9];
    const float* k_b     = (const float*)d_in[10];
    const float* v_w     = (const float*)d_in[11];
    const float* v_b     = (const float*)d_in[12];
    const float* rel_tab = (const float*)d_in[13];
    const float* ln1_g   = (const float*)d_in[14];
    const float* ln1_b   = (const float*)d_in[15];
    const float* ln2_g   = (const float*)d_in[16];
    const float* ln2_b   = (const float*)d_in[17];
    const float* ffn_w1  = (const float*)d_in[18];
    const float* ffn_b1  = (const float*)d_in[19];
    const float* ffn_w2  = (const float*)d_in[20];
    const float* ffn_b2  = (const float*)d_in[21];
    float* out  = (float*)d_out;
    float* pout = out + (size_t)Bsz * Cc * Np;

    GAB(pVh, gV_h)    GAB(pVl, gV_l)
    GAB(pUh, gU_h)    GAB(pUl, gU_l)
    GAF(pM, gM)
    GAB(pqwh, gqw_h)  GAB(pqwl, gqw_l)
    GAB(pkwh, gkw_h)  GAB(pkwl, gkw_l)
    GAB(pvwh, gvw_h)  GAB(pvwl, gvw_l)
    GAB(pw1h, gw1t_h) GAB(pw1l, gw1t_l)
    GAB(pw2fh, gw2f_h) GAB(pw2fl, gw2f_l)
    GAF(pdw, gdown)   GAB(pdth, gdt_h)  GAB(pdtl, gdt_l)
    GAB(pqh, gq_h)    GAB(pql, gq_l)
    GAB(pkh, gk_h)    GAB(pkl, gk_l)
    GAB(pvh, gv_h)    GAB(pvl, gv_l)
    GAF(pqk, gqk)
    GAB(path, gat_h)  GAB(patl, gat_l)
    GAF(ph1p, gh1p)   GAF(ph1, gh1)
    GAB(ph1h, gh1_h)  GAB(ph1l, gh1_l)
    GAB(pfh, gf_h)    GAB(pfl, gf_l)

    cudaFuncSetAttribute(gemm_hm<0>, cudaFuncAttributeMaxDynamicSharedMemorySize, SMEMSZ);
    cudaFuncSetAttribute(gemm_hm<1>, cudaFuncAttributeMaxDynamicSharedMemorySize, SMEMSZ);
    cudaFuncSetAttribute(gemm_hm<3>, cudaFuncAttributeMaxDynamicSharedMemorySize, SMEMSZ);
    cudaFuncSetAttribute(gemm_hm<4>, cudaFuncAttributeMaxDynamicSharedMemorySize, SMEMSZ);
    cudaFuncSetAttribute(gemm_hm<5>, cudaFuncAttributeMaxDynamicSharedMemorySize, SMEMSZ);
    cudaFuncSetAttribute(gemm_hm<6>, cudaFuncAttributeMaxDynamicSharedMemorySize, SMEMSZ);
    cudaFuncSetAttribute(gemm_hm<7>, cudaFuncAttributeMaxDynamicSharedMemorySize, SMEMSZ);

    // launches 1-5 (prep), so launch 6 = Winograd GEMM gets profiled (-s 5 -c 1)
    conv1f_k<<<(Bsz*2500*2304 + 255)/256, 256>>>(x, conv1_w, conv1_b);
    v_trans_k<<<(Bsz*576*2304 + 255)/256, 256>>>();
    u_trans_k<<<(2304*2304 + 255)/256, 256>>>(conv2_w);
    splitk<<<(2304*2304 + 255)/256, 256>>>(q_w, pqwh, pqwl, 2304*2304);
    splitk<<<(2304*2304 + 255)/256, 256>>>(k_w, pkwh, pkwl, 2304*2304);

    // Winograd batched GEMM: M_xi[t][cout] = V_xi[t][:] . U_xi[cout][:], 16 planes
    gemm_hm<7><<<dim3(18,18,16), 256, SMEMSZ>>>(pVh, pVl, pUh, pUl,
        2304, 2304, 2304, PLANE, PLANE, nullptr, nullptr, pM, 2304, PLANE, nullptr, nullptr);

    splitk<<<(2304*2304 + 255)/256, 256>>>(v_w, pvwh, pvwl, 2304*2304);
    tsplit<<<dim3(E2/32, Ee/32), dim3(32,8)>>>(ffn_w1, pw1h, pw1l, Ee, E2);
    tsplit<<<dim3(Ee/32, E2/32), dim3(32,8)>>>(ffn_w2, pw2fh, pw2fl, E2, Ee);

    // Winograd inverse transform (+bias, +identity, +relu) -> down^T
    winv_k<<<(Bsz*576*2304 + 255)/256, 256>>>(x, conv2_b, id_w, id_b);

    // q, k: D[e][p] = qw . down^T
    gemm_hm<0><<<dim3(18,18,Bsz), 256, SMEMSZ>>>(pqwh, pqwl, pdth, pdtl,
        2304, 2304, 2304, 0, PLANE, pqh, pql, nullptr, 2304, PLANE, q_b, nullptr);
    gemm_hm<0><<<dim3(18,18,Bsz), 256, SMEMSZ>>>(pkwh, pkwl, pdth, pdtl,
        2304, 2304, 2304, 0, PLANE, pkh, pkl, nullptr, 2304, PLANE, k_b, nullptr);
    // v^T: D[p][e] = down^T . vw
    gemm_hm<1><<<dim3(18,18,Bsz), 256, SMEMSZ>>>(pdth, pdtl, pvwh, pvwl,
        2304, 2304, 2304, PLANE, 0, pvh, pvl, nullptr, 2304, PLANE, v_b, nullptr);
    // qk = q.k^T/48 + relpos
    gemm_hm<3><<<dim3(18,18,Bsz), 256, SMEMSZ>>>(pqh, pql, pkh, pkl,
        2304, 2304, 2304, PLANE, PLANE, nullptr, nullptr, pqk, 2304, PLANE, rel_tab, nullptr);
    softmax_split_k<<<Bsz*Ee, 256>>>();
    // ao scatter + residual
    gemm_hm<4><<<dim3(18,18,Bsz), 256, SMEMSZ>>>(path, patl, pvh, pvl,
        2304, 2304, 2304, PLANE, PLANE, nullptr, nullptr, ph1p, 2304, 0, nullptr, pdw);
    ln_k<true><<<Bsz*Cc, 256>>>(ph1p, ph1, ph1h, ph1l, ln1_g, ln1_b);
    // ffn1
    gemm_hm<5><<<dim3(72,36,1), 256, SMEMSZ>>>(ph1h, ph1l, pw1h, pw1l,
        2304, 2304, 2304, 0, 0, pfh, pfl, nullptr, E2, 0, ffn_b1, nullptr);
    // ffn2 + residual -> d_out (pre-LN2)
    gemm_hm<6><<<dim3(72,18,1), 256, SMEMSZ>>>(pfh, pfl, pw2fh, pw2fl,
        E2, E2, E2, 0, 0, nullptr, nullptr, out, 2304, 0, ffn_b2, ph1);
    ln_k<false><<<Bsz*Cc, 256>>>(out, out, nullptr, nullptr, ln2_g, ln2_b);
    maxpool_k<<<(Bsz*Cc*576 + 255)/256, 256>>>(out, pout);
}